// round 7
// baseline (speedup 1.0000x reference)
#include <cuda_runtime.h>

// Problem shape (fixed by dataset): source [B,N,3], target [B,M,3], fp32.
#define Bq 2
#define Nq 8192
#define Mq 8192
#define THREADS 256
#define S_PT 4                                  // sources per thread
#define SRC_PER_BLOCK (THREADS * S_PT)          // 1024
#define NCHUNK 128                              // target chunks
#define CHUNK (Mq / NCHUNK)                     // 64 targets per chunk
#define SRCBLK_PER_B (Nq / SRC_PER_BLOCK)       // 8
#define NSRCBLK (Bq * SRCBLK_PER_B)             // 16
#define NBLOCKS (NCHUNK * NSRCBLK)              // 2048
#define BN (Bq * Nq)                            // 16384 sources total

// Scratch (no allocations allowed). g_enc zero-init == identity for the
// descending-encoded max (== float min); the tail block resets it to 0 for
// the next graph replay. g_ticket likewise self-resets.
__device__ unsigned int g_enc[BN];
__device__ int g_ticket;

// Descending order-preserving float->uint encoding: x1 < x2  <=>  enc(x1) > enc(x2).
// Identity for max is 0 -> zero-init is correct.
__device__ __forceinline__ unsigned int enc_desc(float x) {
    unsigned int u = __float_as_uint(x);
    return (u & 0x80000000u) ? u : (~u & 0x7FFFFFFFu);
}

// Single fused kernel, SCALAR FFMA formulation. Each block: 1024 sources x 64
// targets. Targets live in smem as float4 (x, y, z, ht2=0.5*||t||^2) -> one
// broadcast LDS.128 per target. Per pair: d' = ht2 - s.t via 3 FFMA + 1 FMNMX.
// ||s-t*||^2 = ||s||^2 + 2*min(d') recovered in the tail.
// Per-source min folded globally via RED.MAX.U32 on the descending encoding
// (exact, order-independent -> deterministic). Ticketed last block finishes.
__global__ __launch_bounds__(THREADS, 5) void nn_fused_kernel(
    const float* __restrict__ src, const float* __restrict__ tgt,
    float* __restrict__ out) {
    __shared__ __align__(16) float4 tile[CHUNK];
    __shared__ float red[THREADS];
    __shared__ bool is_last;

    const int tid = threadIdx.x;
    const int c = blockIdx.x;                       // target chunk
    const int sb = blockIdx.y;                      // source block
    const int b = sb / SRCBLK_PER_B;
    const int src0 = (sb % SRCBLK_PER_B) * SRC_PER_BLOCK;

    // Build this chunk's target tile (x,y,z,ht2) in smem from AoS global.
    const float* tbase = tgt + (b * Mq + c * CHUNK) * 3;
    if (tid < CHUNK * 3) {
        float v = tbase[tid];
        ((float*)tile)[(tid / 3) * 4 + (tid % 3)] = v;
    }
    __syncthreads();
    if (tid < CHUNK) {
        float4 t = tile[tid];
        tile[tid].w = 0.5f * (t.x * t.x + t.y * t.y + t.z * t.z);
    }

    // Per-thread sources, negated once (12 regs).
    float nsx[S_PT], nsy[S_PT], nsz[S_PT], m[S_PT];
#pragma unroll
    for (int s = 0; s < S_PT; s++) {
        int gi = b * Nq + src0 + s * THREADS + tid;
        nsx[s] = -src[gi * 3 + 0];
        nsy[s] = -src[gi * 3 + 1];
        nsz[s] = -src[gi * 3 + 2];
        m[s] = __int_as_float(0x7f800000);
    }
    __syncthreads();

    // Main loop: 1 broadcast LDS.128 per target, 4 FFMA-chains of depth 3 + min.
#pragma unroll 4
    for (int j = 0; j < CHUNK; j++) {
        float4 t = tile[j];
#pragma unroll
        for (int s = 0; s < S_PT; s++) {
            float d = fmaf(nsx[s], t.x, t.w);
            d = fmaf(nsy[s], t.y, d);
            d = fmaf(nsz[s], t.z, d);
            m[s] = fminf(m[s], d);
        }
    }

    // Fold this block's per-source min into the global min (RED.MAX.U32).
#pragma unroll
    for (int s = 0; s < S_PT; s++) {
        int gi = b * Nq + src0 + s * THREADS + tid;
        atomicMax(&g_enc[gi], enc_desc(m[s]));
    }

    // Ticket: last block of the whole grid finishes the job.
    __threadfence();
    __syncthreads();
    if (tid == 0) {
        int t = atomicAdd(&g_ticket, 1);
        is_last = (t == NBLOCKS - 1);
    }
    __syncthreads();
    if (!is_last) return;

    __threadfence();
    float acc = 0.0f;
#pragma unroll 8
    for (int k = 0; k < BN / THREADS; k++) {
        int gi = k * THREADS + tid;
        unsigned int e = __ldcg(&g_enc[gi]);          // L2 read (skip stale L1)
        unsigned int u = (e & 0x80000000u) ? e : (~e & 0x7FFFFFFFu);
        float mn = __uint_as_float(u);
        float x = src[gi * 3 + 0];
        float y = src[gi * 3 + 1];
        float z = src[gi * 3 + 2];
        acc += x * x + y * y + z * z + 2.0f * mn;     // ||s - t*||^2
    }
    red[tid] = acc;
    __syncthreads();
#pragma unroll
    for (int o = THREADS / 2; o > 0; o >>= 1) {
        if (tid < o) red[tid] += red[tid + o];
        __syncthreads();
    }
    if (tid == 0) {
        out[0] = red[0] * (1.0f / (float)(Bq * Nq * 3));
        g_ticket = 0;                                 // reset for next replay
    }
    // Reset g_enc to the max-identity (0) for the next replay.
#pragma unroll 8
    for (int k = 0; k < BN / THREADS; k++)
        g_enc[k * THREADS + tid] = 0u;
}

extern "C" void kernel_launch(void* const* d_in, const int* in_sizes, int n_in,
                              void* d_out, int out_size) {
    const float* src = (const float*)d_in[0];   // source_point_cloud [B,N,3]
    const float* tgt = (const float*)d_in[1];   // target_point_cloud [B,M,3]
    (void)in_sizes; (void)n_in; (void)out_size;

    nn_fused_kernel<<<dim3(NCHUNK, NSRCBLK), THREADS>>>(src, tgt, (float*)d_out);
}